// round 13
// baseline (speedup 1.0000x reference)
#include <cuda_runtime.h>
#include <cstdint>

#define B_DIM 16
#define P_DIM 4096
#define T_DIM 1024
#define NT    1024
#define EIGHTHS 8
#define TPB   (T_DIM / EIGHTHS)        // 128 targets per block
#define LANES 8                        // NT / TPB lanes per target
#define NBLOCKS (B_DIM * EIGHTHS)      // 128
#define NBINS 256                      // 4 classes * 8x8 cells
#define PPT   (P_DIM / NT)             // 4 preds per thread (contiguous)

// Zero-initialized scratch; last block resets it each call (graph-replay safe).
__device__ unsigned g_mask[B_DIM * (P_DIM / 32)];
__device__ unsigned g_tp;
__device__ unsigned g_done;

__global__ void __launch_bounds__(NT, 1)
loss_kernel(const float* __restrict__ pred, const float* __restrict__ gt,
            float* __restrict__ out)
{
    const int b      = blockIdx.x;
    const int eighth = blockIdx.y;
    const int tid    = threadIdx.x;

    __shared__ float2         s_xy[P_DIM];       // binned pred coords (32KB)
    __shared__ unsigned short s_pid[P_DIM];      // slot -> original pred id (8KB)
    __shared__ unsigned s_hist[NBINS];
    __shared__ unsigned s_scan[NBINS];           // inclusive scan (bin ends)
    __shared__ unsigned s_wsum[8];
    __shared__ int s_last;

    // ---- hoisted target load: overlap its LDG latency with all of binning ----
    const int t = eighth * TPB + (tid >> 3);     // target index
    const int h = tid & 7;                       // lane within target
    const float* te = gt + ((size_t)b * T_DIM + t) * 3;
    const float tcf = te[0];
    const float tx  = te[1];
    const float ty  = te[2];

    if (tid < NBINS) s_hist[tid] = 0u;
    __syncthreads();

    // ---- phase 1: load 4 contiguous preds (3x LDG.128), bin + rank ----
    float px[PPT], py[PPT];
    int   pbin[PPT], prank[PPT];
    {
        const float4* pb4 = (const float4*)(pred + ((size_t)b * P_DIM + tid * PPT) * 3);
        float4 v0 = pb4[0], v1 = pb4[1], v2 = pb4[2];
        float c[PPT];
        c[0]=v0.x; px[0]=v0.y; py[0]=v0.z;
        c[1]=v0.w; px[1]=v1.x; py[1]=v1.y;
        c[2]=v1.z; px[2]=v1.w; py[2]=v2.x;
        c[3]=v2.y; px[3]=v2.z; py[3]=v2.w;
#pragma unroll
        for (int i = 0; i < PPT; i++) {
            int cx = min(7, (int)(px[i] * 0.125f));
            int cy = min(7, (int)(py[i] * 0.125f));
            pbin[i]  = (int)c[i] * 64 + cy * 8 + cx;
            prank[i] = (int)atomicAdd(&s_hist[pbin[i]], 1u);  // rank = scatter slot
        }
    }
    __syncthreads();

    // ---- phase 2: 256-bin inclusive scan (shfl, 2 barriers) ----
    {
        unsigned x = 0;
        const int lane = tid & 31, wid = tid >> 5;
        if (tid < NBINS) {
            x = s_hist[tid];
#pragma unroll
            for (int o = 1; o < 32; o <<= 1) {
                unsigned n = __shfl_up_sync(0xFFFFFFFFu, x, o);
                if (lane >= o) x += n;
            }
            if (lane == 31) s_wsum[wid] = x;
        }
        __syncthreads();
        if (tid == 0) {
            unsigned acc = 0;
#pragma unroll
            for (int w = 0; w < 8; w++) { unsigned v = s_wsum[w]; s_wsum[w] = acc; acc += v; }
        }
        __syncthreads();
        if (tid < NBINS) s_scan[tid] = x + s_wsum[wid];
    }
    __syncthreads();

    // ---- phase 3: scatter using precomputed ranks ----
#pragma unroll
    for (int i = 0; i < PPT; i++) {
        unsigned pos = s_scan[pbin[i]] - s_hist[pbin[i]] + (unsigned)prank[i];
        s_xy[pos]  = make_float2(px[i], py[i]);
        s_pid[pos] = (unsigned short)(tid * PPT + i);
    }
    __syncthreads();

    // ---- phase 4: 8 lanes per target, row-contiguous candidate ranges ----
    int newbit = 0;
    {
        const int   tcls = (int)tcf;
        const int cx0 = max(0, (int)((tx - 5.0f) * 0.125f));
        const int cx1 = min(7, (int)((tx + 5.0f) * 0.125f));
        const int cy0 = max(0, (int)((ty - 5.0f) * 0.125f));
        const int cy1 = min(7, (int)((ty + 5.0f) * 0.125f));

        float bestd2 = __int_as_float(0x7f800000);
        int   bestslot = P_DIM;
        for (int cy = cy0; cy <= cy1; cy++) {
            // bins cls*64+cy*8+cx0 .. +cx1 are consecutive -> contiguous slots
            const int bin0 = tcls * 64 + cy * 8 + cx0;
            const int bin1 = tcls * 64 + cy * 8 + cx1;
            const unsigned start = s_scan[bin0] - s_hist[bin0];
            const unsigned end   = s_scan[bin1];
            for (unsigned s = start + h; s < end; s += LANES) {
                float2 q = s_xy[s];
                float dx = q.x - tx;
                float dy = q.y - ty;
                float d2 = fmaf(dx, dx, dy * dy);
                if (d2 < bestd2) { bestd2 = d2; bestslot = (int)s; }
            }
        }
        // combine the 8 lanes (butterfly)
#pragma unroll
        for (int o = 1; o < LANES; o <<= 1) {
            float od2   = __shfl_xor_sync(0xFFFFFFFFu, bestd2, o);
            int   oslot = __shfl_xor_sync(0xFFFFFFFFu, bestslot, o);
            if (od2 < bestd2 || (od2 == bestd2 && oslot < bestslot)) {
                bestd2 = od2; bestslot = oslot;
            }
        }

        if (h == 0 && bestd2 <= 25.0f) {
            unsigned p   = s_pid[bestslot];
            unsigned bit = 1u << (p & 31u);
            unsigned old = atomicOr(&g_mask[b * (P_DIM / 32) + (p >> 5)], bit);
            newbit = (old & bit) ? 0 : 1;
        }
    }
    int cnt = __syncthreads_count(newbit);

    if (tid == 0) {
        if (cnt) atomicAdd(&g_tp, (unsigned)cnt);
        __threadfence();
        s_last = (atomicAdd(&g_done, 1u) == NBLOCKS - 1);
    }
    __syncthreads();
    if (!s_last) return;

    // ---- last block: compute f1, reset all scratch for next replay ----
    __threadfence();
    for (int i = tid; i < B_DIM * (P_DIM / 32); i += NT) g_mask[i] = 0u;
    if (tid == 0) {
        float tp = (float)atomicAdd(&g_tp, 0u);
        float fp = (float)(B_DIM * P_DIM) - tp;
        float fn = (float)(B_DIM * T_DIM) - tp;
        const float eps = 1e-6f;
        float precision = (tp + eps) / (tp + eps + fp + eps);
        float recall    = (tp + eps) / (tp + fn + eps);
        float f1 = 2.0f * precision * recall / (precision + recall);
        out[0] = 1.0f - f1;
        g_tp = 0u;
        g_done = 0u;
    }
}

extern "C" void kernel_launch(void* const* d_in, const int* in_sizes, int n_in,
                              void* d_out, int out_size) {
    const float* pred = (const float*)d_in[0];
    const float* gt   = (const float*)d_in[1];
    if (n_in >= 2 && in_sizes[0] == B_DIM * T_DIM * 3) {   // swapped-order guard
        pred = (const float*)d_in[1];
        gt   = (const float*)d_in[0];
    }
    float* out = (float*)d_out;

    dim3 grid(B_DIM, EIGHTHS);   // 128 blocks, single wave
    loss_kernel<<<grid, NT>>>(pred, gt, out);
}